// round 12
// baseline (speedup 1.0000x reference)
#include <cuda_runtime.h>

#define BB 256
#define TT 2048
#define PP 64

typedef unsigned long long ull;

// ---------------- device scratch (static, allowed) ----------------
__device__ ull   g_E[32][64];               // g_E[k][c] = pack2(exp(A[2k][c]), exp(A[2k+1][c]))
__device__ float g_logZ[BB];
__device__ float g_nll[BB];
__device__ int   g_lab64;                   // 1 if labels are int64, 0 if int32

// ---------------- f32x2 helpers (sm_103a packed fp32) ----------------
__device__ __forceinline__ ull pack2(float lo, float hi) {
    ull r; asm("mov.b64 %0, {%1,%2};" : "=l"(r) : "f"(lo), "f"(hi)); return r;
}
__device__ __forceinline__ void unpack2(ull v, float& lo, float& hi) {
    asm("mov.b64 {%0,%1}, %2;" : "=f"(lo), "=f"(hi) : "l"(v));
}
__device__ __forceinline__ ull ffma2(ull a, ull b, ull c) {
    ull d; asm("fma.rn.f32x2 %0, %1, %2, %3;" : "=l"(d) : "l"(a), "l"(b), "l"(c)); return d;
}
__device__ __forceinline__ ull fadd2(ull a, ull b) {
    ull d; asm("add.rn.f32x2 %0, %1, %2;" : "=l"(d) : "l"(a), "l"(b)); return d;
}

// ---------------- cp.async helpers ----------------
__device__ __forceinline__ void cp_async4(void* smem, const void* gmem) {
    unsigned s = (unsigned)__cvta_generic_to_shared(smem);
    asm volatile("cp.async.ca.shared.global [%0], [%1], 4;" :: "r"(s), "l"(gmem) : "memory");
}
__device__ __forceinline__ void cp_commit() {
    asm volatile("cp.async.commit_group;" ::: "memory");
}
__device__ __forceinline__ void cp_wait6() {
    asm volatile("cp.async.wait_group 6;" ::: "memory");
}

// ---------------- kernel A0: detect labels dtype ----------------
// Reads only the first TT int32 words (in-bounds under both interpretations).
// int64 labels in [0,64) => every odd 32-bit word is zero.
__global__ void detect_kernel(const int* __restrict__ labels_raw) {
    __shared__ int nz;
    if (threadIdx.x == 0) nz = 0;
    __syncthreads();
    int acc = 0;
    for (int i = threadIdx.x; i < TT / 2; i += blockDim.x)
        acc |= labels_raw[2 * i + 1];
    if (acc) atomicOr(&nz, 1);
    __syncthreads();
    if (threadIdx.x == 0) g_lab64 = (nz == 0) ? 1 : 0;
}

// ---------------- kernel A: precompute E = exp(A), column-packed ----------------
// A in [-0.01, 0.01] => E in [0.99, 1.01]; no stabilization needed.
__global__ void precompute_kernel(const float* __restrict__ A) {
    int c = threadIdx.x;  // 0..63 output column
    for (int k = 0; k < 32; k++) {
        float elo = __expf(A[(2 * k) * PP + c]);
        float ehi = __expf(A[(2 * k + 1) * PP + c]);
        g_E[k][c] = pack2(elo, ehi);
    }
}

// ---------------- kernel B: forward recursion ----------------
// 2 batches per 256-thread CTA; 128 threads per batch; 2 threads per output
// column (input halves h=0/1), 16 FFMA2 each; halves combined with ONE
// shfl.xor(16) inside the warp (columns = 16*warp + lane&15, half = lane>>4).
// Linear recursion q_t = (E^T q_{t-1}) .* (exp(u_t) * 2^-e_t), with e_t =
// exponent field of q[0] (broadcast read, exact pow-2 renorm each step).
__global__ __launch_bounds__(256, 1) void forward_kernel(const float* __restrict__ unary) {
    const int tid  = threadIdx.x;
    const int wid  = tid >> 5;                 // 0..7
    const int lane = tid & 31;
    const int g    = wid >> 2;                 // batch slot in CTA (0/1)
    const int w4   = wid & 3;                  // warp within batch
    const int h    = lane >> 4;                // input half (0/1)
    const int c    = 16 * w4 + (lane & 15);    // owned output column
    const int b    = blockIdx.x * 2 + g;
    const float* Ub = unary + (size_t)b * TT * PP;

    // this thread's 32 inputs of column c: E rows [32h, 32h+32)
    ull Er[16];
#pragma unroll
    for (int k = 0; k < 16; k++) Er[k] = g_E[16 * h + k][c];

    __shared__ __align__(16) float qs[2][2][64];   // per-batch double-buffered q
    __shared__ float us[2][8][64];                 // per-batch unary prefetch ring
    __shared__ float part[2][4];

    // prologue: prefetch u for t=1..7 (h==0 threads cover all 64 columns)
#pragma unroll
    for (int t = 1; t <= 7; ++t) {
        if (h == 0) cp_async4(&us[g][t & 7][c], Ub + (size_t)t * PP + c);
        cp_commit();
    }

    // t = 0 init: q = exp(u0)
    float q = __expf(Ub[c]);
    int eacc = 0;
    qs[g][0][c] = q;
    cp_wait6();                                // slot 1 complete before BAR
    __syncthreads();

#pragma unroll 2
    for (int t = 1; t < TT; ++t) {
        float u = us[g][t & 7][c];
        const float* pin = qs[g][(t + 1) & 1];

        // renorm source: exponent of q[0] (broadcast LDS, off the matvec path)
        unsigned q0bits = __float_as_uint(pin[0]);
        int ef = (int)(q0bits >> 23);
        float sc = __int_as_float((254 - ef) << 23);   // exact 2^-(ef-127)
        eacc += ef - 127;
        float wgt = __expf(u) * sc;

        // half-matvec: partial_c = sum_{i in half} q_i * E[i][c]; 16 FFMA2
        ull a0 = 0ull, a1 = 0ull, a2 = 0ull, a3 = 0ull;
        const float* ph = pin + 32 * h;
#pragma unroll
        for (int m = 0; m < 4; m++) {
            ulonglong2 pa = *(const ulonglong2*)&ph[8 * m];
            ulonglong2 pb = *(const ulonglong2*)&ph[8 * m + 4];
            a0 = ffma2(pa.x, Er[4 * m],     a0);
            a1 = ffma2(pa.y, Er[4 * m + 1], a1);
            a2 = ffma2(pb.x, Er[4 * m + 2], a2);
            a3 = ffma2(pb.y, Er[4 * m + 3], a3);
        }
        ull sp = fadd2(fadd2(a0, a1), fadd2(a2, a3));
        float lo, hi;
        unpack2(sp, lo, hi);
        float partial = lo + hi;

        // combine the two input halves: one intra-warp shfl
        float full = partial + __shfl_xor_sync(0xffffffffu, partial, 16);
        q = full * wgt;

        qs[g][t & 1][c] = q;                   // both halves write same value

        // refill ring 7 steps ahead; wait BEFORE the barrier so h=1 threads
        // safely read h=0-fetched data after __syncthreads
        int tp = t + 7;
        if (h == 0 && tp < TT) cp_async4(&us[g][tp & 7][c], Ub + (size_t)tp * PP + c);
        cp_commit();
        cp_wait6();
        __syncthreads();
    }

    // logZ = ln2 * eacc + log(sum over 64 columns)
    float s = q;
#pragma unroll
    for (int o = 16; o; o >>= 1) s += __shfl_xor_sync(0xffffffffu, s, o);
    if (lane == 0) part[g][w4] = s;            // s = 2 * sum of this warp's 16 cols
    __syncthreads();
    if ((tid & 127) == 0) {
        float tot = 0.5f * (part[g][0] + part[g][1] + part[g][2] + part[g][3]);
        double logZ = (double)eacc * 0.6931471805599453 + log((double)tot);
        g_logZ[b] = (float)logZ;
    }
}

// ---------------- kernel C: emit + transition scores (dtype-robust) ----------------
__global__ void score_kernel(const float* __restrict__ unary,
                             const void* __restrict__ labels,
                             const float* __restrict__ A) {
    const int b = blockIdx.x;
    const float* u = unary + (size_t)b * TT * PP;
    const int lab64 = g_lab64;
    double acc = 0.0;
    if (lab64) {
        const long long* lb = (const long long*)labels + (size_t)b * TT;
        for (int t = threadIdx.x; t < TT; t += blockDim.x) {
            int y = (int)lb[t];
            float v = u[(size_t)t * PP + y];
            float tr = (t > 0) ? A[((int)lb[t - 1]) * PP + y] : 0.0f;
            acc += (double)(v + tr);
        }
    } else {
        const int* lb = (const int*)labels + (size_t)b * TT;
        for (int t = threadIdx.x; t < TT; t += blockDim.x) {
            int y = lb[t];
            float v = u[(size_t)t * PP + y];
            float tr = (t > 0) ? A[lb[t - 1] * PP + y] : 0.0f;
            acc += (double)(v + tr);
        }
    }
    __shared__ double sh[256];
    sh[threadIdx.x] = acc;
    __syncthreads();
    for (int s = 128; s > 0; s >>= 1) {
        if (threadIdx.x < s) sh[threadIdx.x] += sh[threadIdx.x + s];
        __syncthreads();
    }
    if (threadIdx.x == 0) g_nll[b] = g_logZ[b] - (float)sh[0];
}

// ---------------- kernel D: deterministic mean ----------------
__global__ void final_kernel(float* out) {
    __shared__ float sh[BB];
    sh[threadIdx.x] = g_nll[threadIdx.x];
    __syncthreads();
    for (int s = 128; s > 0; s >>= 1) {
        if (threadIdx.x < s) sh[threadIdx.x] += sh[threadIdx.x + s];
        __syncthreads();
    }
    if (threadIdx.x == 0) out[0] = sh[0] / (float)BB;
}

// ---------------- launch ----------------
extern "C" void kernel_launch(void* const* d_in, const int* in_sizes, int n_in,
                              void* d_out, int out_size) {
    const float* unary = (const float*)d_in[0];
    const void* labels = d_in[1];
    const float* A = (const float*)d_in[2];

    detect_kernel<<<1, 128>>>((const int*)labels);
    precompute_kernel<<<1, 64>>>(A);
    forward_kernel<<<BB / 2, 256>>>(unary);
    score_kernel<<<BB, 256>>>(unary, labels, A);
    final_kernel<<<1, BB>>>((float*)d_out);
}